// round 17
// baseline (speedup 1.0000x reference)
#include <cuda_runtime.h>
#include <cuda_bf16.h>
#include <math.h>

#define C_CH   128
#define HW     3136          // 56*56
#define B_SZ   64
#define NCHUNK 8
#define NTOT   (B_SZ * HW)   // 200704 elements per channel
#define HW4    (HW / 4)      // 784 float4 per plane
#define NPLANE (B_SZ * C_CH) // 8192 planes
#define GRID   512           // 4 blocks/SM x 148 = 592 >= 512 (proven safe)
#define NTHR   512           // 16 warps/block -> 64 warps/SM at occ 4
#define MAXP   4             // max planes a warp may grab (4*8192 >> 8192)

// scratch (no device allocation allowed)
__device__ float g_pmax[NPLANE];
__device__ float g_pmin[NPLANE];
__device__ float g_psum[NPLANE];
__device__ float g_avg [C_CH];
__device__ float g_scl [C_CH];
__device__ float g_gam [C_CH];
__device__ float g_bet [C_CH];
__device__ unsigned g_q  = 0;      // plane ticket queue (reset in-kernel)
__device__ unsigned g_b1 = 0;      // barrier counters: generation-based
__device__ unsigned g_b2 = 0;

__device__ __forceinline__ float qbf(float v) {
    return __bfloat162float(__float2bfloat16(v));
}

__device__ __forceinline__ void grid_barrier(unsigned* ctr, int tid) {
    __syncthreads();
    if (tid == 0) {
        __threadfence();                   // publish this block's writes
        unsigned old = atomicAdd(ctr, 1u);
        unsigned target = (old / GRID + 1u) * GRID;
        for (;;) {
            unsigned v;
            asm volatile("ld.volatile.global.u32 %0, [%1];" : "=r"(v) : "l"(ctr));
            if (v >= target) break;
            __nanosleep(64);
        }
    }
    __syncthreads();
}

__global__ void __launch_bounds__(NTHR, 4)
fused_kernel(const float* __restrict__ x,
             const float* __restrict__ gamma,
             const float* __restrict__ beta,
             float* __restrict__ out) {
    const int tid  = threadIdx.x;
    const int lane = tid & 31;

    // ============== phase 1: dynamic per-plane stats ========================
    int plist[MAXP];
    int np = 0;
    while (np < MAXP) {
        unsigned t;
        if (lane == 0) t = atomicAdd(&g_q, 1u);
        t = __shfl_sync(0xFFFFFFFFu, t, 0);
        if (t >= (unsigned)NPLANE) break;          // one overshoot grab max
        const int p = (int)t;
        plist[np++] = p;

        const float4* px = reinterpret_cast<const float4*>(x) + (size_t)p * HW4;
        float vmax = -INFINITY, vmin = INFINITY, vsum = 0.0f;

        #define ACC4(V)                                                          \
            vmax = fmaxf(vmax, fmaxf(fmaxf((V).x, (V).y), fmaxf((V).z, (V).w))); \
            vmin = fminf(vmin, fminf(fminf((V).x, (V).y), fminf((V).z, (V).w))); \
            vsum += (qbf((V).x) + qbf((V).y)) + (qbf((V).z) + qbf((V).w));

        // 784 = 6*128 + 16 : six rounds of 4 front-batched float4 + tail
        #pragma unroll
        for (int r = 0; r < 6; ++r) {
            const int b = r * 128 + lane;
            float4 v0 = px[b];
            float4 v1 = px[b + 32];
            float4 v2 = px[b + 64];
            float4 v3 = px[b + 96];
            ACC4(v0) ACC4(v1) ACC4(v2) ACC4(v3)
        }
        if (lane < 16) {
            float4 v = px[768 + lane];
            ACC4(v)
        }
        #undef ACC4

        #pragma unroll
        for (int o = 16; o > 0; o >>= 1) {
            vmax = fmaxf(vmax, __shfl_down_sync(0xFFFFFFFFu, vmax, o));
            vmin = fminf(vmin, __shfl_down_sync(0xFFFFFFFFu, vmin, o));
            vsum +=            __shfl_down_sync(0xFFFFFFFFu, vsum, o);
        }
        if (lane == 0) {
            g_pmax[p] = vmax;   // raw; quantized at chunk level (monotonic)
            g_pmin[p] = vmin;
            g_psum[p] = vsum;
        }
    }

    // ============== barrier 1: all stats published ==========================
    grid_barrier(&g_b1, tid);

    // reset the queue for the next launch (all grabs are done; launches are
    // strictly serialized, so this is race-free)
    if (blockIdx.x == 0 && tid == 0) g_q = 0;

    // ============== finalize: blocks 0..15 -> global scalars ================
    __shared__ float sp_m[B_SZ][8], sp_n[B_SZ][8], sp_s[B_SZ][8];
    __shared__ float sc_m[NCHUNK][8], sc_n[NCHUNK][8], sc_s[NCHUNK][8];
    if (blockIdx.x < 16) {
        const int c0f = blockIdx.x * 8;
        {   // stage 1: one (batch, channel) cell per thread, coalesced
            const int g = tid & 7;
            const int j = tid >> 3;               // batch 0..63
            const int idx = j * C_CH + c0f + g;
            sp_m[j][g] = __ldcg(&g_pmax[idx]);
            sp_n[j][g] = __ldcg(&g_pmin[idx]);
            sp_s[j][g] = __ldcg(&g_psum[idx]);
        }
        __syncthreads();
        if (tid < 64) {                           // stage 2: chunk reduce
            const int g = tid & 7;
            const int k = tid >> 3;               // chunk 0..7
            float m = sp_m[8 * k][g], n = sp_n[8 * k][g], s = sp_s[8 * k][g];
            #pragma unroll
            for (int i = 1; i < 8; ++i) {
                m = fmaxf(m, sp_m[8 * k + i][g]);
                n = fminf(n, sp_n[8 * k + i][g]);
                s +=         sp_s[8 * k + i][g];
            }
            sc_m[k][g] = qbf(m);                  // q(chunk max)
            sc_n[k][g] = qbf(n);
            sc_s[k][g] = s;
        }
        __syncthreads();
        if (tid < 8) {                            // stage 3: channel scalars
            const int g = tid;
            const int c = c0f + g;
            float sm = 0.f, sn = 0.f, st = 0.f;
            #pragma unroll
            for (int k = 0; k < NCHUNK; ++k) {
                sm += sc_m[k][g];
                sn += sc_n[k][g];
                st += sc_s[k][g];
            }
            const float sum_max = qbf(sm);
            const float sum_min = qbf(sn);
            const float avg_max = qbf(sum_max / (float)NCHUNK);
            const float avg_min = qbf(sum_min / (float)NCHUNK);
            const float total   = qbf(st);

            const double chunk_size = (double)(NCHUNK * HW);  // 25088
            const float scale_fix = (float)(1.0 / sqrt(2.0 * log(chunk_size)));

            g_avg[c] = qbf(total / (float)NTOT);
            g_scl[c] = qbf(1.0f / ((avg_max - avg_min) * scale_fix + 1e-5f));
            g_gam[c] = qbf(gamma[c]);
            g_bet[c] = beta[c];
        }
    }

    // ============== barrier 2: scalars published ============================
    grid_barrier(&g_b2, tid);

    // ============== phase 2: normalize remembered planes ====================
    // Reverse grab order + reversed rounds: the most recently L1-cached lines
    // (L1 persists within the launch) are re-read first.
    for (int i = np - 1; i >= 0; --i) {
        const int p = plist[i];
        const int c = p & (C_CH - 1);

        const float avg   = g_avg[c];     // fresh: first touch this launch
        const float scale = g_scl[c];
        const float gm    = g_gam[c];
        const float be    = g_bet[c];

        const float4* px = reinterpret_cast<const float4*>(x)   + (size_t)p * HW4;
        float4*       po = reinterpret_cast<float4*>(out)       + (size_t)p * HW4;

        float4 r; float t;
        #define NORM4(V, R)                                                \
            t = qbf((qbf((V).x) - avg) * scale); (R).x = qbf(t * gm + be); \
            t = qbf((qbf((V).y) - avg) * scale); (R).y = qbf(t * gm + be); \
            t = qbf((qbf((V).z) - avg) * scale); (R).z = qbf(t * gm + be); \
            t = qbf((qbf((V).w) - avg) * scale); (R).w = qbf(t * gm + be);

        if (lane < 16) {                         // tail was read last in phase 1
            float4 v = __ldcs(px + 768 + lane);
            NORM4(v, r); __stcs(po + 768 + lane, r);
        }
        #pragma unroll
        for (int rr = 5; rr >= 0; --rr) {        // 6 rounds of 128 f4, reversed
            const int b = rr * 128 + lane;
            float4 v0 = __ldcs(px + b);
            float4 v1 = __ldcs(px + b + 32);
            float4 v2 = __ldcs(px + b + 64);
            float4 v3 = __ldcs(px + b + 96);
            NORM4(v0, r); __stcs(po + b,      r);
            NORM4(v1, r); __stcs(po + b + 32, r);
            NORM4(v2, r); __stcs(po + b + 64, r);
            NORM4(v3, r); __stcs(po + b + 96, r);
        }
        #undef NORM4
    }
}

// ---------------------------------------------------------------------------
extern "C" void kernel_launch(void* const* d_in, const int* in_sizes, int n_in,
                              void* d_out, int out_size) {
    const float* x     = (const float*)d_in[0];
    const float* gamma = (const float*)d_in[1];
    const float* beta  = (const float*)d_in[2];
    float* out = (float*)d_out;

    fused_kernel<<<GRID, NTHR>>>(x, gamma, beta, out);
}